// round 12
// baseline (speedup 1.0000x reference)
#include <cuda_runtime.h>
#include <math.h>

#define NN 2048
#define MM 128
#define KD 8
#define K2 64
#define NPACK 36
#define NPB 4             // children per block (4 groups of 8 lanes in warp 0)
#define NB (NN / NPB)     // 512 chunks per t
#define NPAR 16           // parent producer blocks
#define FULLM 0xffffffffu

// ---------------- scratch --------------------------------------------------
__device__ float4 g_C4[2][11][MM];   // 44 coefs per m: 36 Bp + 8 (-h), SoA over m
__device__ float  g_dm[2][MM];       // -log|det O| + 0.5 logdetS - 4 + 0.5 ee
__device__ double g_part[2][NB];
__device__ volatile unsigned int g_ready;
__device__ unsigned int g_done;

// ---------------- f32x2 helpers --------------------------------------------
__device__ __forceinline__ void ffma2(unsigned long long& d,
                                      unsigned long long a, unsigned long long b) {
    asm("fma.rn.f32x2 %0, %1, %2, %0;" : "+l"(d) : "l"(a), "l"(b));
}
__device__ __forceinline__ float2 unpack2(unsigned long long v) {
    float2 f;
    asm("mov.b64 {%0, %1}, %2;" : "=f"(f.x), "=f"(f.y) : "l"(v));
    return f;
}

// ==================== single fused kernel ====================================
__global__ __launch_bounds__(128)
void main_kernel(const float* __restrict__ W,
                 const float* __restrict__ mu_p, const float* __restrict__ sigma_p,
                 const float* __restrict__ omega_child,
                 const float* __restrict__ mu_q, const float* __restrict__ sigma_q,
                 const float* __restrict__ omega_parent,
                 const float* __restrict__ mu_r, const float* __restrict__ sigma_r,
                 const float* __restrict__ omega_m_child,
                 const float* __restrict__ mu_s, const float* __restrict__ sigma_s,
                 const float* __restrict__ omega_m_parent,
                 float* __restrict__ out) {
    const int t  = blockIdx.y;
    const int m  = threadIdx.x;
    const int n0 = blockIdx.x * NPB;

    // ---- W prefetch first (longest latency; in flight through all phases) --
    float wv[NPB];
#pragma unroll
    for (int k = 0; k < NPB; k++) wv[k] = W[(n0 + k) * MM + m];

    // ================= parent phase: bids 0..15 of y==0 ====================
    if (blockIdx.y == 0 && blockIdx.x < NPAR) {
        const int g = m >> 3;     // group 0..15
        const int r = m & 7;
        const int gid = blockIdx.x * 16 + g;       // 0..255
        const int tp = gid >> 7;
        const int mp = gid & (MM - 1);
        const float* mup = (tp == 0) ? mu_q : mu_s;
        const float* Sp  = (tp == 0) ? sigma_q : sigma_s;
        const float* Op  = (tp == 0) ? omega_parent : omega_m_parent;

        float orow[KD], srow[KD], irow[KD], trow[KD];
        {
            const float4* o4 = reinterpret_cast<const float4*>(Op + (size_t)mp * K2 + r * KD);
            const float4* s4 = reinterpret_cast<const float4*>(Sp + (size_t)mp * K2 + r * KD);
            float4 a = o4[0], b = o4[1], c = s4[0], d = s4[1];
            orow[0] = a.x; orow[1] = a.y; orow[2] = a.z; orow[3] = a.w;
            orow[4] = b.x; orow[5] = b.y; orow[6] = b.z; orow[7] = b.w;
            srow[0] = c.x; srow[1] = c.y; srow[2] = c.z; srow[3] = c.w;
            srow[4] = d.x; srow[5] = d.y; srow[6] = d.z; srow[7] = d.w;
        }
        float mur = mup[mp * KD + r];
#pragma unroll
        for (int j = 0; j < KD; j++) irow[j] = (j == r) ? 1.f : 0.f;

        // row-parallel GJ inverse of SPD S; pivot product = det S
        float pdS = 1.f;
#pragma unroll
        for (int kk = 0; kk < KD; kk++) {
            float piv = __shfl_sync(FULLM, srow[kk], kk, 8);
            pdS *= piv;
            float ip = 1.f / piv;
            if (r == kk) {
#pragma unroll
                for (int j = 0; j < KD; j++) { srow[j] *= ip; irow[j] *= ip; }
            }
            float f = (r == kk) ? 0.f : srow[kk];
#pragma unroll
            for (int j = 0; j < KD; j++) {
                float ps = __shfl_sync(FULLM, srow[j], kk, 8);
                float pi = __shfl_sync(FULLM, irow[j], kk, 8);
                srow[j] = fmaf(-f, ps, srow[j]);
                irow[j] = fmaf(-f, pi, irow[j]);
            }
        }
        // u = Sinv*mu
        float ur = 0.f;
#pragma unroll
        for (int b = 0; b < KD; b++)
            ur = fmaf(irow[b], __shfl_sync(FULLM, mur, b, 8), ur);
        // T = Sinv*Omega (row r)
#pragma unroll
        for (int j = 0; j < KD; j++) trow[j] = 0.f;
#pragma unroll
        for (int b = 0; b < KD; b++) {
            float ib = irow[b];
#pragma unroll
            for (int j = 0; j < KD; j++)
                trow[j] = fmaf(ib, __shfl_sync(FULLM, orow[j], b, 8), trow[j]);
        }
        // ee = mu.u
        float ee = mur * ur;
        ee += __shfl_xor_sync(FULLM, ee, 1, 8);
        ee += __shfl_xor_sync(FULLM, ee, 2, 8);
        ee += __shfl_xor_sync(FULLM, ee, 4, 8);

        __shared__ float Osh[16][KD][KD], Tsh[16][KD][KD], ush[16][KD];
#pragma unroll
        for (int j = 0; j < KD; j++) { Osh[g][r][j] = orow[j]; Tsh[g][r][j] = trow[j]; }
        ush[g][r] = ur;
        __syncwarp();

        float* cbase = reinterpret_cast<float*>(g_C4) + (size_t)tp * 11 * MM * 4;
        const int pbase = r * KD - (r * (r - 1)) / 2 - r;
#pragma unroll
        for (int j = 0; j < KD; j++) {
            if (j < r) continue;
            float b = 0.f;
#pragma unroll
            for (int a = 0; a < KD; a++) b = fmaf(Osh[g][a][r], Tsh[g][a][j], b);
            if (j == r) b *= 0.5f;
            int c = pbase + j;
            cbase[(size_t)(c >> 2) * MM * 4 + mp * 4 + (c & 3)] = b;
        }
        {
            float h = 0.f;
#pragma unroll
            for (int a = 0; a < KD; a++) h = fmaf(Osh[g][a][r], ush[g][a], h);
            int c = NPACK + r;
            cbase[(size_t)(c >> 2) * MM * 4 + mp * 4 + (c & 3)] = -h;
        }
        // det Omega
        float pdO = 1.f;
#pragma unroll
        for (int kk = 0; kk < KD; kk++) {
            float piv = __shfl_sync(FULLM, orow[kk], kk, 8);
            pdO *= piv;
            float ipv = 1.f / piv;
            float f = (r > kk) ? orow[kk] * ipv : 0.f;
#pragma unroll
            for (int j = 0; j < KD; j++) {
                float pk = __shfl_sync(FULLM, orow[j], kk, 8);
                orow[j] = fmaf(-f, pk, orow[j]);
            }
        }
        if (r == 0)
            g_dm[tp][mp] = -logf(fabsf(pdO)) + 0.5f * logf(pdS) - 4.0f + 0.5f * ee;

        __threadfence();
        __syncthreads();
        if (m == 0) atomicAdd((unsigned int*)&g_ready, 1u);
    }

    // ================= child phase: warp 0, 4 groups of 8 ==================
    __shared__ __align__(16) float sh[NPB][48];
    if (m < 32) {
        const int grp = m >> 3;
        const int r   = m & 7;
        const int n   = n0 + grp;
        const float* muc = (t == 0) ? mu_p    : mu_r;
        const float* Sc  = (t == 0) ? sigma_p : sigma_r;
        const float* Oc  = (t == 0) ? omega_child : omega_m_child;

        float orow[KD], srow[KD], irow[KD];
        {
            const float4* o4 = reinterpret_cast<const float4*>(Oc + (size_t)n * K2 + r * KD);
            const float4* s4 = reinterpret_cast<const float4*>(Sc + (size_t)n * K2 + r * KD);
            float4 a = o4[0], b = o4[1], c = s4[0], d = s4[1];
            orow[0] = a.x; orow[1] = a.y; orow[2] = a.z; orow[3] = a.w;
            orow[4] = b.x; orow[5] = b.y; orow[6] = b.z; orow[7] = b.w;
            srow[0] = c.x; srow[1] = c.y; srow[2] = c.z; srow[3] = c.w;
            srow[4] = d.x; srow[5] = d.y; srow[6] = d.z; srow[7] = d.w;
        }
        float mur = muc[n * KD + r];
#pragma unroll
        for (int j = 0; j < KD; j++) irow[j] = (j == r) ? 1.f : 0.f;

        // row-parallel GJ: irow -> row r of Omega^{-1}
        float pd = 1.f;
#pragma unroll
        for (int kk = 0; kk < KD; kk++) {
            float piv = __shfl_sync(FULLM, orow[kk], kk, 8);
            pd *= piv;
            float ip = 1.f / piv;
            if (r == kk) {
#pragma unroll
                for (int j = 0; j < KD; j++) { orow[j] *= ip; irow[j] *= ip; }
            }
            float f = (r == kk) ? 0.f : orow[kk];
#pragma unroll
            for (int j = 0; j < KD; j++) {
                float pko = __shfl_sync(FULLM, orow[j], kk, 8);
                float pki = __shfl_sync(FULLM, irow[j], kk, 8);
                orow[j] = fmaf(-f, pko, orow[j]);
                irow[j] = fmaf(-f, pki, irow[j]);
            }
        }
        // v_r
        float vr = 0.f;
#pragma unroll
        for (int j = 0; j < KD; j++)
            vr = fmaf(irow[j], __shfl_sync(FULLM, mur, j, 8), vr);
        // trow = row r of Oi*S
        float trow[KD] = {0.f, 0.f, 0.f, 0.f, 0.f, 0.f, 0.f, 0.f};
#pragma unroll
        for (int b = 0; b < KD; b++) {
            float ob = irow[b];
#pragma unroll
            for (int c = 0; c < KD; c++)
                trow[c] = fmaf(ob, __shfl_sync(FULLM, srow[c], b, 8), trow[c]);
        }
        // Atilde row r -> packed upper in shared
        float* rec = &sh[grp][0];
        const int base = r * KD - (r * (r - 1)) / 2;
#pragma unroll
        for (int j = 0; j < KD; j++) {
            float aij = vr * __shfl_sync(FULLM, vr, j, 8);
#pragma unroll
            for (int c = 0; c < KD; c++)
                aij = fmaf(trow[c], __shfl_sync(FULLM, irow[c], j, 8), aij);
            if (j >= r) rec[base + j - r] = aij;
        }
        rec[NPACK + r] = vr;
        // det(S)
        float pd2 = 1.f;
#pragma unroll
        for (int kk = 0; kk < KD; kk++) {
            float piv = __shfl_sync(FULLM, srow[kk], kk, 8);
            pd2 *= piv;
            float ipv = 1.f / piv;
            float f = (r > kk) ? srow[kk] * ipv : 0.f;
#pragma unroll
            for (int j = 0; j < KD; j++) {
                float pks = __shfl_sync(FULLM, srow[j], kk, 8);
                srow[j] = fmaf(-f, pks, srow[j]);
            }
        }
        if (r == 0) rec[44] = logf(fabsf(pd)) - 0.5f * logf(pd2);
    }

    // ---- wait for parent coefs (short; parents are wave-1 and fast) ----
    if (m == 0) {
        while (g_ready < NPAR) { }
    }
    __syncthreads();
    __threadfence();

    // ---- coef loads ----
    float4 c4[11];
#pragma unroll
    for (int q = 0; q < 11; q++) c4[q] = g_C4[t][q][m];
    const float dm = g_dm[t][m];
    const unsigned long long* c2 = reinterpret_cast<const unsigned long long*>(c4);

    // ---- pair phase ----
    float accf = 0.f;
#pragma unroll
    for (int k = 0; k < NPB; k++) {
        const unsigned long long* a2 =
            reinterpret_cast<const unsigned long long*>(&sh[k][0]);
        unsigned long long acc0 = 0ull, acc1 = 0ull;
#pragma unroll
        for (int p = 0; p < 22; p += 2) {
            ffma2(acc0, c2[p], a2[p]);
            ffma2(acc1, c2[p + 1], a2[p + 1]);
        }
        float2 s0 = unpack2(acc0);
        float2 s1 = unpack2(acc1);
        float kl = (s0.x + s0.y) + (s1.x + s1.y) + (dm + sh[k][44]);
        accf = fmaf(wv[k], kl, accf);
    }

    // ---- fp32 warp reduce -> fp64 block partial, ticket finalize ----
#pragma unroll
    for (int off = 16; off; off >>= 1)
        accf += __shfl_down_sync(FULLM, accf, off);
    __shared__ float wsumf[4];
    __shared__ int islast;
    if ((m & 31) == 0) wsumf[m >> 5] = accf;
    __syncthreads();
    if (m == 0) {
        g_part[t][blockIdx.x] =
            (double)wsumf[0] + (double)wsumf[1] + (double)wsumf[2] + (double)wsumf[3];
        __threadfence();
        unsigned int tick = atomicAdd(&g_done, 1u);
        islast = (tick == 2u * NB - 1u) ? 1 : 0;
    }
    __syncthreads();
    if (islast) {
        __threadfence();
        double s0 = g_part[0][m] + g_part[0][m + 128] +
                    g_part[0][m + 256] + g_part[0][m + 384];
        double s1 = g_part[1][m] + g_part[1][m + 128] +
                    g_part[1][m + 256] + g_part[1][m + 384];
#pragma unroll
        for (int off = 16; off; off >>= 1) {
            s0 += __shfl_down_sync(FULLM, s0, off);
            s1 += __shfl_down_sync(FULLM, s1, off);
        }
        __shared__ double ws0[4], ws1[4];
        if ((m & 31) == 0) { ws0[m >> 5] = s0; ws1[m >> 5] = s1; }
        __syncthreads();
        if (m == 0) {
            double b  = ws0[0] + ws0[1] + ws0[2] + ws0[3];
            double mo = ws1[0] + ws1[1] + ws1[2] + ws1[3];
            out[0] = (float)(b + mo);
            out[1] = (float)b;
            out[2] = (float)mo;
            g_done = 0u;     // reset for next graph replay
            g_ready = 0u;
        }
    }
}

// ----------------------------------------------------------------------------
extern "C" void kernel_launch(void* const* d_in, const int* in_sizes, int n_in,
                              void* d_out, int out_size) {
    const float* W              = (const float*)d_in[0];
    const float* mu_p           = (const float*)d_in[1];
    const float* sigma_p        = (const float*)d_in[2];
    const float* mu_q_parent    = (const float*)d_in[3];
    const float* sigma_q_parent = (const float*)d_in[4];
    const float* omega_child    = (const float*)d_in[5];
    const float* omega_parent   = (const float*)d_in[6];
    const float* mu_r           = (const float*)d_in[7];
    const float* sigma_r        = (const float*)d_in[8];
    const float* mu_s_parent    = (const float*)d_in[9];
    const float* sigma_s_parent = (const float*)d_in[10];
    const float* omega_m_child  = (const float*)d_in[11];
    const float* omega_m_parent = (const float*)d_in[12];

    main_kernel<<<dim3(NB, 2), MM>>>(W,
                                     mu_p, sigma_p, omega_child,
                                     mu_q_parent, sigma_q_parent, omega_parent,
                                     mu_r, sigma_r, omega_m_child,
                                     mu_s_parent, sigma_s_parent, omega_m_parent,
                                     (float*)d_out);
}

// round 13
// speedup vs baseline: 2.2047x; 2.2047x over previous
#include <cuda_runtime.h>
#include <math.h>

#define NN 2048
#define MM 128
#define KD 8
#define K2 64
#define NPACK 36
#define CH 16              // children per chunk
#define NCH (NN / CH)      // 128 chunks
#define NP 48              // aggregate vector length: 36 A + 8 v + cc + w + 2 pad
#define FULLM 0xffffffffu

// ---------------- scratch --------------------------------------------------
__device__ float  g_pl[2][NCH][NP][MM];  // stage-1 partials
__device__ float  g_At[2][NP][MM];       // reduced aggregates Ã
__device__ double g_fin[2][8];
__device__ unsigned int g_done1;         // reset by stage2's last block
__device__ unsigned int g_done2;

// ---------------- f32x2 helpers --------------------------------------------
__device__ __forceinline__ unsigned long long pack2(float a, float b) {
    unsigned long long r;
    asm("mov.b64 %0, {%1, %2};" : "=l"(r) : "f"(a), "f"(b));
    return r;
}
__device__ __forceinline__ void ffma2(unsigned long long& d,
                                      unsigned long long a, unsigned long long b) {
    asm("fma.rn.f32x2 %0, %1, %2, %0;" : "+l"(d) : "l"(a), "l"(b));
}
__device__ __forceinline__ float2 unpack2(unsigned long long v) {
    float2 f;
    asm("mov.b64 {%0, %1}, %2;" : "=f"(f.x), "=f"(f.y) : "l"(v));
    return f;
}

// ==================== stage 1: children + weighted aggregation ===============
__global__ __launch_bounds__(128)
void stage1_kernel(const float* __restrict__ W,
                   const float* __restrict__ mu_p, const float* __restrict__ sigma_p,
                   const float* __restrict__ omega_child,
                   const float* __restrict__ mu_r, const float* __restrict__ sigma_r,
                   const float* __restrict__ omega_m_child) {
    const int t = blockIdx.y;
    const int c = blockIdx.x;          // chunk 0..127
    const int n0 = c * CH;
    const int m = threadIdx.x;

    // W prefetch (in flight through child phase)
    float wv[CH];
#pragma unroll
    for (int k = 0; k < CH; k++) wv[k] = W[(n0 + k) * MM + m];

    // ---- child phase: 16 groups of 8 lanes (validated R9/R11 math) ----
    const int g = m >> 3, r = m & 7;
    const int n = n0 + g;
    const float* muc = (t == 0) ? mu_p    : mu_r;
    const float* Sc  = (t == 0) ? sigma_p : sigma_r;
    const float* Oc  = (t == 0) ? omega_child : omega_m_child;

    __shared__ __align__(16) float4 sh4[CH][12];
    float* rec = reinterpret_cast<float*>(&sh4[g][0]);
    {
        float orow[KD], srow[KD], irow[KD];
        {
            const float4* o4 = reinterpret_cast<const float4*>(Oc + (size_t)n * K2 + r * KD);
            const float4* s4 = reinterpret_cast<const float4*>(Sc + (size_t)n * K2 + r * KD);
            float4 a = o4[0], b = o4[1], cc4 = s4[0], d = s4[1];
            orow[0] = a.x; orow[1] = a.y; orow[2] = a.z; orow[3] = a.w;
            orow[4] = b.x; orow[5] = b.y; orow[6] = b.z; orow[7] = b.w;
            srow[0] = cc4.x; srow[1] = cc4.y; srow[2] = cc4.z; srow[3] = cc4.w;
            srow[4] = d.x; srow[5] = d.y; srow[6] = d.z; srow[7] = d.w;
        }
        float mur = muc[n * KD + r];
#pragma unroll
        for (int j = 0; j < KD; j++) irow[j] = (j == r) ? 1.f : 0.f;

        // row-parallel GJ: irow -> row r of Omega^{-1}; det via pivots
        float pd = 1.f;
#pragma unroll
        for (int kk = 0; kk < KD; kk++) {
            float piv = __shfl_sync(FULLM, orow[kk], kk, 8);
            pd *= piv;
            float ip = 1.f / piv;
            if (r == kk) {
#pragma unroll
                for (int j = 0; j < KD; j++) { orow[j] *= ip; irow[j] *= ip; }
            }
            float f = (r == kk) ? 0.f : orow[kk];
#pragma unroll
            for (int j = 0; j < KD; j++) {
                float pko = __shfl_sync(FULLM, orow[j], kk, 8);
                float pki = __shfl_sync(FULLM, irow[j], kk, 8);
                orow[j] = fmaf(-f, pko, orow[j]);
                irow[j] = fmaf(-f, pki, irow[j]);
            }
        }
        // v_r
        float vr = 0.f;
#pragma unroll
        for (int j = 0; j < KD; j++)
            vr = fmaf(irow[j], __shfl_sync(FULLM, mur, j, 8), vr);
        // trow = row r of Oi*S
        float trow[KD] = {0.f, 0.f, 0.f, 0.f, 0.f, 0.f, 0.f, 0.f};
#pragma unroll
        for (int b = 0; b < KD; b++) {
            float ob = irow[b];
#pragma unroll
            for (int cc2 = 0; cc2 < KD; cc2++)
                trow[cc2] = fmaf(ob, __shfl_sync(FULLM, srow[cc2], b, 8), trow[cc2]);
        }
        // Atilde row r -> packed upper in shared
        const int base = r * KD - (r * (r - 1)) / 2;
#pragma unroll
        for (int j = 0; j < KD; j++) {
            float aij = vr * __shfl_sync(FULLM, vr, j, 8);
#pragma unroll
            for (int cc2 = 0; cc2 < KD; cc2++)
                aij = fmaf(trow[cc2], __shfl_sync(FULLM, irow[cc2], j, 8), aij);
            if (j >= r) rec[base + j - r] = aij;
        }
        rec[NPACK + r] = vr;
        // det(S) forward elimination
        float pd2 = 1.f;
#pragma unroll
        for (int kk = 0; kk < KD; kk++) {
            float piv = __shfl_sync(FULLM, srow[kk], kk, 8);
            pd2 *= piv;
            float ipv = 1.f / piv;
            float f = (r > kk) ? srow[kk] * ipv : 0.f;
#pragma unroll
            for (int j = 0; j < KD; j++) {
                float pks = __shfl_sync(FULLM, srow[j], kk, 8);
                srow[j] = fmaf(-f, pks, srow[j]);
            }
        }
        if (r == 0) rec[44] = logf(fabsf(pd)) - 0.5f * logf(pd2);
        if (r == 1) { rec[45] = 1.f; rec[46] = 0.f; rec[47] = 0.f; }
    }
    __syncthreads();

    // ---- weighted aggregation: acc[p] = sum_k wv[k]*rec_k[p], f32x2 ----
    unsigned long long acc2[24];
#pragma unroll
    for (int j = 0; j < 24; j++) acc2[j] = 0ull;
#pragma unroll
    for (int k = 0; k < CH; k++) {
        unsigned long long w2 = pack2(wv[k], wv[k]);
        const unsigned long long* a2 =
            reinterpret_cast<const unsigned long long*>(&sh4[k][0]);
#pragma unroll
        for (int j = 0; j < 24; j++) ffma2(acc2[j], w2, a2[j]);
    }

    // coalesced partial store [t][c][p][m]
#pragma unroll
    for (int j = 0; j < 24; j++) {
        float2 f = unpack2(acc2[j]);
        g_pl[t][c][2 * j][m]     = f.x;
        g_pl[t][c][2 * j + 1][m] = f.y;
    }

    __threadfence();
    __syncthreads();
    if (m == 0) atomicAdd(&g_done1, 1u);

    // ---- adopters (c < NP): symmetric short wait, then reduce one p ----
    if (c < NP) {
        if (m == 0) {
            while (*((volatile unsigned int*)&g_done1) < 2u * NCH) { }
        }
        __syncthreads();
        __threadfence();
        const int p = c;
        float s = 0.f;
        const float* src = &g_pl[t][0][p][m];
#pragma unroll 8
        for (int cc2 = 0; cc2 < NCH; cc2++)
            s += src[(size_t)cc2 * NP * MM];
        g_At[t][p][m] = s;
    }
}

// ==================== stage 2: parents + final combine =======================
__global__ __launch_bounds__(128)
void stage2_kernel(const float* __restrict__ mu_q, const float* __restrict__ sigma_q,
                   const float* __restrict__ omega_parent,
                   const float* __restrict__ mu_s, const float* __restrict__ sigma_s,
                   const float* __restrict__ omega_m_parent,
                   float* __restrict__ out) {
    const int t = blockIdx.y;
    const int m0 = blockIdx.x * 16;    // grid (8, 2)
    const int tid = threadIdx.x;
    const int g = tid >> 3, r = tid & 7;
    const int mp = m0 + g;

    const float* mup = (t == 0) ? mu_q : mu_s;
    const float* Sp  = (t == 0) ? sigma_q : sigma_s;
    const float* Op  = (t == 0) ? omega_parent : omega_m_parent;

    // ---- validated row-parallel parent math ----
    float orow[KD], srow[KD], irow[KD], trow[KD];
    {
        const float4* o4 = reinterpret_cast<const float4*>(Op + (size_t)mp * K2 + r * KD);
        const float4* s4 = reinterpret_cast<const float4*>(Sp + (size_t)mp * K2 + r * KD);
        float4 a = o4[0], b = o4[1], cc4 = s4[0], d = s4[1];
        orow[0] = a.x; orow[1] = a.y; orow[2] = a.z; orow[3] = a.w;
        orow[4] = b.x; orow[5] = b.y; orow[6] = b.z; orow[7] = b.w;
        srow[0] = cc4.x; srow[1] = cc4.y; srow[2] = cc4.z; srow[3] = cc4.w;
        srow[4] = d.x; srow[5] = d.y; srow[6] = d.z; srow[7] = d.w;
    }
    float mur = mup[mp * KD + r];
#pragma unroll
    for (int j = 0; j < KD; j++) irow[j] = (j == r) ? 1.f : 0.f;

    // GJ inverse of SPD S; pivot product = det S
    float pdS = 1.f;
#pragma unroll
    for (int kk = 0; kk < KD; kk++) {
        float piv = __shfl_sync(FULLM, srow[kk], kk, 8);
        pdS *= piv;
        float ip = 1.f / piv;
        if (r == kk) {
#pragma unroll
            for (int j = 0; j < KD; j++) { srow[j] *= ip; irow[j] *= ip; }
        }
        float f = (r == kk) ? 0.f : srow[kk];
#pragma unroll
        for (int j = 0; j < KD; j++) {
            float ps = __shfl_sync(FULLM, srow[j], kk, 8);
            float pi = __shfl_sync(FULLM, irow[j], kk, 8);
            srow[j] = fmaf(-f, ps, srow[j]);
            irow[j] = fmaf(-f, pi, irow[j]);
        }
    }
    // u = Sinv*mu
    float ur = 0.f;
#pragma unroll
    for (int b = 0; b < KD; b++)
        ur = fmaf(irow[b], __shfl_sync(FULLM, mur, b, 8), ur);
    // T = Sinv*Omega (row r)
#pragma unroll
    for (int j = 0; j < KD; j++) trow[j] = 0.f;
#pragma unroll
    for (int b = 0; b < KD; b++) {
        float ib = irow[b];
#pragma unroll
        for (int j = 0; j < KD; j++)
            trow[j] = fmaf(ib, __shfl_sync(FULLM, orow[j], b, 8), trow[j]);
    }
    // ee = mu.u
    float ee = mur * ur;
    ee += __shfl_xor_sync(FULLM, ee, 1, 8);
    ee += __shfl_xor_sync(FULLM, ee, 2, 8);
    ee += __shfl_xor_sync(FULLM, ee, 4, 8);

    __shared__ float Osh[16][KD][KD], Tsh[16][KD][KD], ush[16][KD];
#pragma unroll
    for (int j = 0; j < KD; j++) { Osh[g][r][j] = orow[j]; Tsh[g][r][j] = trow[j]; }
    ush[g][r] = ur;
    __syncwarp();

    // b8[j] = (O^T Sinv O)_rj with 0.5 on diag; hr = (O^T Sinv mu)_r
    float b8[KD];
#pragma unroll
    for (int j = 0; j < KD; j++) {
        float b = 0.f;
#pragma unroll
        for (int a = 0; a < KD; a++) b = fmaf(Osh[g][a][r], Tsh[g][a][j], b);
        b8[j] = (j == r) ? 0.5f * b : b;
    }
    float hr = 0.f;
#pragma unroll
    for (int a = 0; a < KD; a++) hr = fmaf(Osh[g][a][r], ush[g][a], hr);

    // det Omega (forward elimination)
    float pdO = 1.f;
#pragma unroll
    for (int kk = 0; kk < KD; kk++) {
        float piv = __shfl_sync(FULLM, orow[kk], kk, 8);
        pdO *= piv;
        float ipv = 1.f / piv;
        float f = (r > kk) ? orow[kk] * ipv : 0.f;
#pragma unroll
        for (int j = 0; j < KD; j++) {
            float pk = __shfl_sync(FULLM, orow[j], kk, 8);
            orow[j] = fmaf(-f, pk, orow[j]);
        }
    }
    float dm = 0.f;
    if (r == 0)
        dm = -logf(fabsf(pdO)) + 0.5f * logf(pdS) - 4.0f + 0.5f * ee;

    // ---- final combine with aggregates ----
    float part = -hr * g_At[t][NPACK + r][mp];
    const int base = r * KD - (r * (r - 1)) / 2;
#pragma unroll
    for (int j = 0; j < KD; j++)
        if (j >= r) part += b8[j] * g_At[t][base + j - r][mp];
    if (r == 0) part += dm * g_At[t][45][mp] + g_At[t][44][mp];
    part += __shfl_xor_sync(FULLM, part, 1, 8);
    part += __shfl_xor_sync(FULLM, part, 2, 8);
    part += __shfl_xor_sync(FULLM, part, 4, 8);

    __shared__ float gres[16];
    if (r == 0) gres[g] = part;
    __syncthreads();
    if (tid == 0) {
        double s = 0.0;
        for (int i = 0; i < 16; i++) s += (double)gres[i];
        g_fin[t][blockIdx.x] = s;
        __threadfence();
        unsigned int tick = atomicAdd(&g_done2, 1u);
        if (tick == 15u) {
            __threadfence();
            double b = 0.0, mo = 0.0;
            for (int i = 0; i < 8; i++) { b += g_fin[0][i]; mo += g_fin[1][i]; }
            out[0] = (float)(b + mo);
            out[1] = (float)b;
            out[2] = (float)mo;
            g_done1 = 0u;      // reset for next graph replay
            g_done2 = 0u;
        }
    }
}

// ----------------------------------------------------------------------------
extern "C" void kernel_launch(void* const* d_in, const int* in_sizes, int n_in,
                              void* d_out, int out_size) {
    const float* W              = (const float*)d_in[0];
    const float* mu_p           = (const float*)d_in[1];
    const float* sigma_p        = (const float*)d_in[2];
    const float* mu_q_parent    = (const float*)d_in[3];
    const float* sigma_q_parent = (const float*)d_in[4];
    const float* omega_child    = (const float*)d_in[5];
    const float* omega_parent   = (const float*)d_in[6];
    const float* mu_r           = (const float*)d_in[7];
    const float* sigma_r        = (const float*)d_in[8];
    const float* mu_s_parent    = (const float*)d_in[9];
    const float* sigma_s_parent = (const float*)d_in[10];
    const float* omega_m_child  = (const float*)d_in[11];
    const float* omega_m_parent = (const float*)d_in[12];

    stage1_kernel<<<dim3(NCH, 2), MM>>>(W, mu_p, sigma_p, omega_child,
                                        mu_r, sigma_r, omega_m_child);
    stage2_kernel<<<dim3(8, 2), MM>>>(mu_q_parent, sigma_q_parent, omega_parent,
                                      mu_s_parent, sigma_s_parent, omega_m_parent,
                                      (float*)d_out);
}